// round 14
// baseline (speedup 1.0000x reference)
#include <cuda_runtime.h>

#define D_IN   187
#define H_HID  50
#define C_OUT  5
#define LPR    4            // lanes per row
#define HP     13           // h per lane (52 padded)
#define TPB    128
#define RPB    (TPB/LPR)    // 32 rows per block
#define TQ     3            // timesteps per relay hop
#define DCH    48           // d-chunk (4 chunks: 48*3 + 43)
#define SXP    52           // sx row pitch: 16B-aligned, bases mod 32 distinct
#define THR    1.0f
#define BETA   0.9f

typedef unsigned long long u64;

// packed f32x2 helpers (two independent RN fp32 ops -> bit-identical to scalar)
#define FMA2(acc, s, w) asm("fma.rn.f32x2 %0, %1, %2, %0;" : "+l"(acc) : "l"(s), "l"(w))
#define DUP2(d, f)      asm("mov.b64 %0, {%1, %1};" : "=l"(d) : "f"(f))
#define UNPK2(lo, hi, d) asm("mov.b64 {%0, %1}, %2;" : "=f"(lo), "=f"(hi) : "l"(d))

// Shared layout (floats):
//  sW1: [dloc][j*20+i] pitch 80/d; lane 128b bases {0,20,8,28} mod 32 conflict-free
//  sW2: [h][8] (h padded to 52); per-hh 16B loads at h*32B -> conflict-free
//  sx : [r][SXP]
#define SM_W1   0
#define SM_W1_SZ (DCH * 80)              // 3840
#define SM_W2   (SM_W1 + SM_W1_SZ)
#define SM_W2_SZ (52 * 8)                // 416
#define SM_X    (SM_W2 + SM_W2_SZ)
#define SM_X_SZ (RPB * SXP)              // 1664
#define SMEM_BYTES ((SM_X + SM_X_SZ) * 4)   // 23680 B -> 7 blocks/SM

__global__ __launch_bounds__(TPB, 7)
void snn_fused_kernel(const float* __restrict__ x,
                      const float* __restrict__ W1,
                      const float* __restrict__ b1,
                      const float* __restrict__ W2,
                      const float* __restrict__ b2,
                      float* __restrict__ out,
                      int B, int steps)
{
    extern __shared__ float smem[];
    float* sW1 = smem + SM_W1;
    float* sW2 = smem + SM_W2;
    float* sx  = smem + SM_X;

    const int tid   = threadIdx.x;
    const int j     = tid & (LPR - 1);
    const int rloc  = tid >> 2;
    const int row   = blockIdx.x * RPB + rloc;
    const bool rowv = (row < B);
    const int hbase = j * HP;

    // ---- stage W2 [h][8], h>=50 zero ----
    for (int idx = tid; idx < 52 * C_OUT; idx += TPB) {
        int h = idx % 52, c = idx / 52;
        sW2[h * 8 + c] = (h < H_HID) ? W2[c * H_HID + h] : 0.0f;
    }

    // ---- phase 1: cur1 via exact ascending-k fma chains, packed f32x2 ----
    u64 A01 = 0ull, A23 = 0ull, A45 = 0ull, A67 = 0ull, A89 = 0ull, Aab = 0ull;
    float a12 = 0.0f;

    for (int d0 = 0; d0 < D_IN; d0 += DCH) {
        const int len = (D_IN - d0 < DCH) ? (D_IN - d0) : DCH;
        __syncthreads();
        for (int idx = tid; idx < 52 * len; idx += TPB) {
            int h = idx % 52, dloc = idx / 52;
            float v = (h < H_HID) ? W1[h * D_IN + d0 + dloc] : 0.0f;
            sW1[dloc * 80 + (h / HP) * 20 + (h % HP)] = v;
        }
        for (int i2 = tid; i2 < RPB * len; i2 += TPB) {
            int r  = i2 / len;
            int dl = i2 - r * len;
            int gr = blockIdx.x * RPB + r;
            sx[r * SXP + dl] = (gr < B) ? x[(size_t)gr * D_IN + d0 + dl] : 0.0f;
        }
        __syncthreads();
        const float* xbase = &sx[rloc * SXP];
        const float* wbase = &sW1[j * 20];

#define GEMM_BODY(XV, DL) do {                                            \
            const float* wp = wbase + (DL) * 80;                          \
            u64 xd; DUP2(xd, (XV));                                       \
            ulonglong2 wA = *(const ulonglong2*)(wp);                     \
            ulonglong2 wB = *(const ulonglong2*)(wp + 4);                 \
            ulonglong2 wC = *(const ulonglong2*)(wp + 8);                 \
            float w12 = wp[12];                                           \
            FMA2(A01, xd, wA.x); FMA2(A23, xd, wA.y);                     \
            FMA2(A45, xd, wB.x); FMA2(A67, xd, wB.y);                     \
            FMA2(A89, xd, wC.x); FMA2(Aab, xd, wC.y);                     \
            a12 = fmaf(w12, (XV), a12);                                   \
        } while (0)

        const int q4 = len >> 2;
        const float4* xq = (const float4*)xbase;
        for (int g = 0; g < q4; ++g) {
            float4 xv4 = xq[g];
            GEMM_BODY(xv4.x, 4 * g + 0);
            GEMM_BODY(xv4.y, 4 * g + 1);
            GEMM_BODY(xv4.z, 4 * g + 2);
            GEMM_BODY(xv4.w, 4 * g + 3);
        }
        for (int dl = q4 * 4; dl < len; ++dl) {
            GEMM_BODY(xbase[dl], dl);
        }
#undef GEMM_BODY
    }

    // unpack accumulators, bias as separate rounded add; pad h -> 0
    float cur1[HP];
    UNPK2(cur1[0],  cur1[1],  A01);
    UNPK2(cur1[2],  cur1[3],  A23);
    UNPK2(cur1[4],  cur1[5],  A45);
    UNPK2(cur1[6],  cur1[7],  A67);
    UNPK2(cur1[8],  cur1[9],  A89);
    UNPK2(cur1[10], cur1[11], Aab);
    cur1[12] = a12;
#pragma unroll
    for (int i = 0; i < HP; ++i) {
        int h = hbase + i;
        cur1[i] = (h < H_HID) ? __fadd_rn(cur1[i], b1[h]) : 0.0f;
    }

    // ---- phase 2: T=3 relay. Lane j handles quad p = i - j (t = 3p..3p+2).
    // Each t's 50-term cur2 chain stays exactly serial across lanes (shfl
    // relay); 3 timesteps per hop -> 9 independent packed accumulate chains
    // and W2 LDS amortized over 9 FMAs. Pad h never spikes: exact no-ops.
    // Final quads may compute mem1 past steps: dead values, never stored.
    float mem1[HP];
#pragma unroll
    for (int i = 0; i < HP; ++i) mem1[i] = 0.0f;

    u64 P01[TQ], P23[TQ];      // packed partial c2 (cols 0-1, 2-3) per step
    float P4[TQ];              // col 4
#pragma unroll
    for (int k = 0; k < TQ; ++k) { P01[k] = 0ull; P23[k] = 0ull; P4[k] = 0.0f; }

    float mem2[C_OUT], rb2[C_OUT];
#pragma unroll
    for (int c = 0; c < C_OUT; ++c) { mem2[c] = 0.0f; rb2[c] = b2[c]; }

    const size_t memoff = (size_t)steps * B * C_OUT;
    const size_t bstr   = (size_t)B * C_OUT;
    const int nquads = (steps + TQ - 1) / TQ;
    const int iters  = nquads + LPR - 1;
    const bool storer = (j == LPR - 1) && rowv;
    const float* w2p = &sW2[hbase * 8];

    for (int i = 0; i < iters; ++i) {
        u64 q01[TQ], q23[TQ];
        float q4v[TQ];
#pragma unroll
        for (int k = 0; k < TQ; ++k) {
            q01[k] = __shfl_up_sync(0xFFFFFFFFu, P01[k], 1, LPR);
            q23[k] = __shfl_up_sync(0xFFFFFFFFu, P23[k], 1, LPR);
            q4v[k] = __shfl_up_sync(0xFFFFFFFFu, P4[k], 1, LPR);
        }

        const int p = i - j;
        if ((unsigned)p < (unsigned)nquads) {
            u64 a01[TQ], a23[TQ];
            float a4[TQ];
#pragma unroll
            for (int k = 0; k < TQ; ++k) {
                a01[k] = (j == 0) ? 0ull : q01[k];
                a23[k] = (j == 0) ? 0ull : q23[k];
                a4[k]  = (j == 0) ? 0.0f : q4v[k];
            }

#pragma unroll
            for (int hh = 0; hh < HP; ++hh) {
                // W2 from shared: one 16B + one 4B load per hh per hop
                const ulonglong2 wp2 = *(const ulonglong2*)(w2p + hh * 8);
                const float w4 = w2p[hh * 8 + 4];
                float m = mem1[hh];
                const float c1 = cur1[hh];
                float r = (m > THR) ? 1.0f : 0.0f;   // reset from prev mem
#pragma unroll
                for (int k = 0; k < TQ; ++k) {
                    m = __fsub_rn(fmaf(BETA, m, c1), r);
                    const float s = (m > THR) ? 1.0f : 0.0f;
                    r = s;                            // spike(t) == reset(t+1)
                    u64 sd; DUP2(sd, s);
                    FMA2(a01[k], sd, wp2.x);
                    FMA2(a23[k], sd, wp2.y);
                    a4[k] = fmaf(s, w4, a4[k]);
                }
                mem1[hh] = m;
            }
#pragma unroll
            for (int k = 0; k < TQ; ++k) {
                P01[k] = a01[k]; P23[k] = a23[k]; P4[k] = a4[k];
            }

            if (storer) {
                const int t0 = TQ * p;
#pragma unroll
                for (int k = 0; k < TQ; ++k) {
                    const int t = t0 + k;
                    if (t < steps) {
                        float f0, f1, f2, f3;
                        UNPK2(f0, f1, P01[k]);
                        UNPK2(f2, f3, P23[k]);
                        const float f4 = P4[k];
                        const size_t ob = (size_t)t * bstr + (size_t)row * C_OUT;
                        float F[C_OUT] = {f0, f1, f2, f3, f4};
#pragma unroll
                        for (int c = 0; c < C_OUT; ++c) {
                            const float cur2 = __fadd_rn(F[c], rb2[c]); // dot + b2
                            float m2 = mem2[c];
                            const float r2 = (m2 > THR) ? 1.0f : 0.0f;
                            m2 = __fsub_rn(fmaf(BETA, m2, cur2), r2);
                            mem2[c] = m2;
                            out[ob + c]          = (m2 > THR) ? 1.0f : 0.0f;
                            out[memoff + ob + c] = m2;
                        }
                    }
                }
            }
        }
    }
}

extern "C" void kernel_launch(void* const* d_in, const int* in_sizes, int n_in,
                              void* d_out, int out_size)
{
    const float* x  = (const float*)d_in[0];
    const float* W1 = (const float*)d_in[1];
    const float* b1 = (const float*)d_in[2];
    const float* W2 = (const float*)d_in[3];
    const float* b2 = (const float*)d_in[4];
    float* out = (float*)d_out;

    const int B = in_sizes[0] / D_IN;
    const int steps = (int)((long long)out_size / (2LL * B * C_OUT));

    cudaFuncSetAttribute(snn_fused_kernel,
                         cudaFuncAttributeMaxDynamicSharedMemorySize, SMEM_BYTES);

    const int grid = (B + RPB - 1) / RPB;
    snn_fused_kernel<<<grid, TPB, SMEM_BYTES>>>(x, W1, b1, W2, b2, out, B, steps);
}

// round 15
// speedup vs baseline: 1.0411x; 1.0411x over previous
#include <cuda_runtime.h>

#define D_IN   187
#define H_HID  50
#define C_OUT  5
#define LPR    4            // lanes per row-group
#define HP     13           // h per lane (52 padded)
#define TPB    128
#define RPB    64           // rows per block (2 rows per lane group)
#define TQ     2            // timesteps per relay hop
#define DCH    48           // d-chunk (4 chunks: 48*3 + 43)
#define SXP    52           // sx row pitch: 16B-aligned, bases mod 32 distinct
#define THR    1.0f
#define BETA   0.9f

typedef unsigned long long u64;

// packed f32x2 helpers (two independent RN fp32 ops -> bit-identical to scalar)
#define FMA2(acc, s, w) asm("fma.rn.f32x2 %0, %1, %2, %0;" : "+l"(acc) : "l"(s), "l"(w))
#define DUP2(d, f)      asm("mov.b64 %0, {%1, %1};" : "=l"(d) : "f"(f))
#define UNPK2(lo, hi, d) asm("mov.b64 {%0, %1}, %2;" : "=f"(lo), "=f"(hi) : "l"(d))

// Shared layout (floats):
//  sW1: [dloc][j*20+i] pitch 80/d; lane 128b bases {0,20,8,28} mod 32 conflict-free
//  sW2: [h][8] (h padded to 52); per-hh 16B loads at h*32B -> conflict-free
//  sx : [r][SXP], r in 0..63
#define SM_W1   0
#define SM_W1_SZ (DCH * 80)              // 3840
#define SM_W2   (SM_W1 + SM_W1_SZ)
#define SM_W2_SZ (52 * 8)                // 416
#define SM_X    (SM_W2 + SM_W2_SZ)
#define SM_X_SZ (RPB * SXP)              // 3328
#define SMEM_BYTES ((SM_X + SM_X_SZ) * 4)   // 30336 B -> 4 blocks/SM

__global__ __launch_bounds__(TPB, 4)
void snn_fused_kernel(const float* __restrict__ x,
                      const float* __restrict__ W1,
                      const float* __restrict__ b1,
                      const float* __restrict__ W2,
                      const float* __restrict__ b2,
                      float* __restrict__ out,
                      int B, int steps)
{
    extern __shared__ float smem[];
    float* sW1 = smem + SM_W1;
    float* sW2 = smem + SM_W2;
    float* sx  = smem + SM_X;

    const int tid   = threadIdx.x;
    const int j     = tid & (LPR - 1);
    const int rloc  = tid >> 2;                 // 0..31
    const int rowA  = blockIdx.x * RPB + rloc;
    const int rowB  = rowA + 32;
    const bool vA   = (rowA < B);
    const bool vB   = (rowB < B);
    const int hbase = j * HP;

    // ---- stage W2 [h][8], h>=50 zero ----
    for (int idx = tid; idx < 52 * C_OUT; idx += TPB) {
        int h = idx % 52, c = idx / 52;
        sW2[h * 8 + c] = (h < H_HID) ? W2[c * H_HID + h] : 0.0f;
    }

    // ---- phase 1: cur1 for BOTH rows; exact ascending-k fma chains (f32x2) ----
    u64 A01a = 0, A23a = 0, A45a = 0, A67a = 0, A89a = 0, Aaba = 0;
    u64 A01b = 0, A23b = 0, A45b = 0, A67b = 0, A89b = 0, Aabb = 0;
    float a12a = 0.0f, a12b = 0.0f;

    for (int d0 = 0; d0 < D_IN; d0 += DCH) {
        const int len = (D_IN - d0 < DCH) ? (D_IN - d0) : DCH;
        __syncthreads();
        for (int idx = tid; idx < 52 * len; idx += TPB) {
            int h = idx % 52, dloc = idx / 52;
            float v = (h < H_HID) ? W1[h * D_IN + d0 + dloc] : 0.0f;
            sW1[dloc * 80 + (h / HP) * 20 + (h % HP)] = v;
        }
        for (int i2 = tid; i2 < RPB * len; i2 += TPB) {
            int r  = i2 / len;
            int dl = i2 - r * len;
            int gr = blockIdx.x * RPB + r;
            sx[r * SXP + dl] = (gr < B) ? x[(size_t)gr * D_IN + d0 + dl] : 0.0f;
        }
        __syncthreads();
        const float* xA = &sx[rloc * SXP];
        const float* xB = &sx[(rloc + 32) * SXP];
        const float* wbase = &sW1[j * 20];

#define GEMM_BODY(XVA, XVB, DL) do {                                      \
            const float* wp = wbase + (DL) * 80;                          \
            ulonglong2 wA = *(const ulonglong2*)(wp);                     \
            ulonglong2 wB = *(const ulonglong2*)(wp + 4);                 \
            ulonglong2 wC = *(const ulonglong2*)(wp + 8);                 \
            float w12 = wp[12];                                           \
            u64 xda; DUP2(xda, (XVA));                                    \
            u64 xdb; DUP2(xdb, (XVB));                                    \
            FMA2(A01a, xda, wA.x); FMA2(A23a, xda, wA.y);                 \
            FMA2(A45a, xda, wB.x); FMA2(A67a, xda, wB.y);                 \
            FMA2(A89a, xda, wC.x); FMA2(Aaba, xda, wC.y);                 \
            a12a = fmaf(w12, (XVA), a12a);                                \
            FMA2(A01b, xdb, wA.x); FMA2(A23b, xdb, wA.y);                 \
            FMA2(A45b, xdb, wB.x); FMA2(A67b, xdb, wB.y);                 \
            FMA2(A89b, xdb, wC.x); FMA2(Aabb, xdb, wC.y);                 \
            a12b = fmaf(w12, (XVB), a12b);                                \
        } while (0)

        const int q4 = len >> 2;
        const float4* xqA = (const float4*)xA;
        const float4* xqB = (const float4*)xB;
        for (int g = 0; g < q4; ++g) {
            float4 va = xqA[g];
            float4 vb = xqB[g];
            GEMM_BODY(va.x, vb.x, 4 * g + 0);
            GEMM_BODY(va.y, vb.y, 4 * g + 1);
            GEMM_BODY(va.z, vb.z, 4 * g + 2);
            GEMM_BODY(va.w, vb.w, 4 * g + 3);
        }
        for (int dl = q4 * 4; dl < len; ++dl) {
            GEMM_BODY(xA[dl], xB[dl], dl);
        }
#undef GEMM_BODY
    }

    // unpack; bias as separate rounded add; pad h -> 0
    float cur1A[HP], cur1B[HP];
    UNPK2(cur1A[0],  cur1A[1],  A01a); UNPK2(cur1A[2],  cur1A[3],  A23a);
    UNPK2(cur1A[4],  cur1A[5],  A45a); UNPK2(cur1A[6],  cur1A[7],  A67a);
    UNPK2(cur1A[8],  cur1A[9],  A89a); UNPK2(cur1A[10], cur1A[11], Aaba);
    cur1A[12] = a12a;
    UNPK2(cur1B[0],  cur1B[1],  A01b); UNPK2(cur1B[2],  cur1B[3],  A23b);
    UNPK2(cur1B[4],  cur1B[5],  A45b); UNPK2(cur1B[6],  cur1B[7],  A67b);
    UNPK2(cur1B[8],  cur1B[9],  A89b); UNPK2(cur1B[10], cur1B[11], Aabb);
    cur1B[12] = a12b;
#pragma unroll
    for (int i = 0; i < HP; ++i) {
        int h = hbase + i;
        cur1A[i] = (h < H_HID) ? __fadd_rn(cur1A[i], b1[h]) : 0.0f;
        cur1B[i] = (h < H_HID) ? __fadd_rn(cur1B[i], b1[h]) : 0.0f;
    }

    // ---- phase 2: pair-relay over 2 rows. Lane j handles pair p = i - j
    // (t = 2p, 2p+1) for BOTH rows -> 2x independent work per thread (ILP).
    // Each t's 50-term cur2 chain stays exactly serial across lanes (shfl
    // relay). W2 via shared, 2 LDS per hh per hop serving 20 FMAs.
    float m1A[HP], m1B[HP];
#pragma unroll
    for (int i = 0; i < HP; ++i) { m1A[i] = 0.0f; m1B[i] = 0.0f; }

    // packed partials per row: [01][23] per step + col4 scalars
    u64 PA01a = 0, PA23a = 0, PB01a = 0, PB23a = 0;   // row A, steps A/B
    u64 PA01b = 0, PA23b = 0, PB01b = 0, PB23b = 0;   // row B
    float PA4a = 0, PB4a = 0, PA4b = 0, PB4b = 0;

    float mem2A[C_OUT], mem2B[C_OUT], rb2[C_OUT];
#pragma unroll
    for (int c = 0; c < C_OUT; ++c) { mem2A[c] = 0.0f; mem2B[c] = 0.0f; rb2[c] = b2[c]; }

    const size_t memoff = (size_t)steps * B * C_OUT;
    const size_t bstr   = (size_t)B * C_OUT;
    const int npairs = (steps + 1) >> 1;
    const int iters  = npairs + LPR - 1;
    const bool storer = (j == LPR - 1);
    const float* w2p = &sW2[hbase * 8];

    for (int i = 0; i < iters; ++i) {
        u64 qA01a = __shfl_up_sync(0xFFFFFFFFu, PA01a, 1, LPR);
        u64 qA23a = __shfl_up_sync(0xFFFFFFFFu, PA23a, 1, LPR);
        u64 qB01a = __shfl_up_sync(0xFFFFFFFFu, PB01a, 1, LPR);
        u64 qB23a = __shfl_up_sync(0xFFFFFFFFu, PB23a, 1, LPR);
        float qA4a = __shfl_up_sync(0xFFFFFFFFu, PA4a, 1, LPR);
        float qB4a = __shfl_up_sync(0xFFFFFFFFu, PB4a, 1, LPR);
        u64 qA01b = __shfl_up_sync(0xFFFFFFFFu, PA01b, 1, LPR);
        u64 qA23b = __shfl_up_sync(0xFFFFFFFFu, PA23b, 1, LPR);
        u64 qB01b = __shfl_up_sync(0xFFFFFFFFu, PB01b, 1, LPR);
        u64 qB23b = __shfl_up_sync(0xFFFFFFFFu, PB23b, 1, LPR);
        float qA4b = __shfl_up_sync(0xFFFFFFFFu, PA4b, 1, LPR);
        float qB4b = __shfl_up_sync(0xFFFFFFFFu, PB4b, 1, LPR);

        const int p = i - j;
        if ((unsigned)p < (unsigned)npairs) {
            const bool z = (j == 0);
            u64 aA01a = z ? 0 : qA01a, aA23a = z ? 0 : qA23a;
            u64 aB01a = z ? 0 : qB01a, aB23a = z ? 0 : qB23a;
            u64 aA01b = z ? 0 : qA01b, aA23b = z ? 0 : qA23b;
            u64 aB01b = z ? 0 : qB01b, aB23b = z ? 0 : qB23b;
            float aA4a = z ? 0.0f : qA4a, aB4a = z ? 0.0f : qB4a;
            float aA4b = z ? 0.0f : qA4b, aB4b = z ? 0.0f : qB4b;

#pragma unroll
            for (int hh = 0; hh < HP; ++hh) {
                const ulonglong2 wp2 = *(const ulonglong2*)(w2p + hh * 8);
                const float w4 = w2p[hh * 8 + 4];
                // row A
                {
                    const float mo = m1A[hh], c1 = cur1A[hh];
                    const float r0 = (mo > THR) ? 1.0f : 0.0f;
                    const float m1 = __fsub_rn(fmaf(BETA, mo, c1), r0);
                    const float s1 = (m1 > THR) ? 1.0f : 0.0f;
                    const float m2 = __fsub_rn(fmaf(BETA, m1, c1), s1);
                    m1A[hh] = m2;
                    const float s2 = (m2 > THR) ? 1.0f : 0.0f;
                    u64 s1d; DUP2(s1d, s1);
                    u64 s2d; DUP2(s2d, s2);
                    FMA2(aA01a, s1d, wp2.x); FMA2(aA23a, s1d, wp2.y);
                    aA4a = fmaf(s1, w4, aA4a);
                    FMA2(aB01a, s2d, wp2.x); FMA2(aB23a, s2d, wp2.y);
                    aB4a = fmaf(s2, w4, aB4a);
                }
                // row B
                {
                    const float mo = m1B[hh], c1 = cur1B[hh];
                    const float r0 = (mo > THR) ? 1.0f : 0.0f;
                    const float m1 = __fsub_rn(fmaf(BETA, mo, c1), r0);
                    const float s1 = (m1 > THR) ? 1.0f : 0.0f;
                    const float m2 = __fsub_rn(fmaf(BETA, m1, c1), s1);
                    m1B[hh] = m2;
                    const float s2 = (m2 > THR) ? 1.0f : 0.0f;
                    u64 s1d; DUP2(s1d, s1);
                    u64 s2d; DUP2(s2d, s2);
                    FMA2(aA01b, s1d, wp2.x); FMA2(aA23b, s1d, wp2.y);
                    aA4b = fmaf(s1, w4, aA4b);
                    FMA2(aB01b, s2d, wp2.x); FMA2(aB23b, s2d, wp2.y);
                    aB4b = fmaf(s2, w4, aB4b);
                }
            }
            PA01a = aA01a; PA23a = aA23a; PB01a = aB01a; PB23a = aB23a;
            PA4a = aA4a; PB4a = aB4a;
            PA01b = aA01b; PA23b = aA23b; PB01b = aB01b; PB23b = aB23b;
            PA4b = aA4b; PB4b = aB4b;

            if (storer) {
                const int t1 = 2 * p;
                const int t2 = t1 + 1;
                const bool hasB = (t2 < steps);
                float F[2 * C_OUT];

                // row A outputs
                if (vA) {
                    UNPK2(F[0], F[1], PA01a); UNPK2(F[2], F[3], PA23a); F[4] = PA4a;
                    UNPK2(F[5], F[6], PB01a); UNPK2(F[7], F[8], PB23a); F[9] = PB4a;
                    const size_t ob1 = (size_t)t1 * bstr + (size_t)rowA * C_OUT;
#pragma unroll
                    for (int c = 0; c < C_OUT; ++c) {
                        const float cur2 = __fadd_rn(F[c], rb2[c]);
                        float m2 = mem2A[c];
                        const float r2 = (m2 > THR) ? 1.0f : 0.0f;
                        m2 = __fsub_rn(fmaf(BETA, m2, cur2), r2);
                        mem2A[c] = m2;
                        out[ob1 + c]          = (m2 > THR) ? 1.0f : 0.0f;
                        out[memoff + ob1 + c] = m2;
                    }
                    if (hasB) {
                        const size_t ob2 = ob1 + bstr;
#pragma unroll
                        for (int c = 0; c < C_OUT; ++c) {
                            const float cur2 = __fadd_rn(F[5 + c], rb2[c]);
                            float m2 = mem2A[c];
                            const float r2 = (m2 > THR) ? 1.0f : 0.0f;
                            m2 = __fsub_rn(fmaf(BETA, m2, cur2), r2);
                            mem2A[c] = m2;
                            out[ob2 + c]          = (m2 > THR) ? 1.0f : 0.0f;
                            out[memoff + ob2 + c] = m2;
                        }
                    }
                }
                // row B outputs
                if (vB) {
                    UNPK2(F[0], F[1], PA01b); UNPK2(F[2], F[3], PA23b); F[4] = PA4b;
                    UNPK2(F[5], F[6], PB01b); UNPK2(F[7], F[8], PB23b); F[9] = PB4b;
                    const size_t ob1 = (size_t)t1 * bstr + (size_t)rowB * C_OUT;
#pragma unroll
                    for (int c = 0; c < C_OUT; ++c) {
                        const float cur2 = __fadd_rn(F[c], rb2[c]);
                        float m2 = mem2B[c];
                        const float r2 = (m2 > THR) ? 1.0f : 0.0f;
                        m2 = __fsub_rn(fmaf(BETA, m2, cur2), r2);
                        mem2B[c] = m2;
                        out[ob1 + c]          = (m2 > THR) ? 1.0f : 0.0f;
                        out[memoff + ob1 + c] = m2;
                    }
                    if (hasB) {
                        const size_t ob2 = ob1 + bstr;
#pragma unroll
                        for (int c = 0; c < C_OUT; ++c) {
                            const float cur2 = __fadd_rn(F[5 + c], rb2[c]);
                            float m2 = mem2B[c];
                            const float r2 = (m2 > THR) ? 1.0f : 0.0f;
                            m2 = __fsub_rn(fmaf(BETA, m2, cur2), r2);
                            mem2B[c] = m2;
                            out[ob2 + c]          = (m2 > THR) ? 1.0f : 0.0f;
                            out[memoff + ob2 + c] = m2;
                        }
                    }
                }
            }
        }
    }
}

extern "C" void kernel_launch(void* const* d_in, const int* in_sizes, int n_in,
                              void* d_out, int out_size)
{
    const float* x  = (const float*)d_in[0];
    const float* W1 = (const float*)d_in[1];
    const float* b1 = (const float*)d_in[2];
    const float* W2 = (const float*)d_in[3];
    const float* b2 = (const float*)d_in[4];
    float* out = (float*)d_out;

    const int B = in_sizes[0] / D_IN;
    const int steps = (int)((long long)out_size / (2LL * B * C_OUT));

    cudaFuncSetAttribute(snn_fused_kernel,
                         cudaFuncAttributeMaxDynamicSharedMemorySize, SMEM_BYTES);

    const int grid = (B + RPB - 1) / RPB;
    snn_fused_kernel<<<grid, TPB, SMEM_BYTES>>>(x, W1, b1, W2, b2, out, B, steps);
}